// round 6
// baseline (speedup 1.0000x reference)
#include <cuda_runtime.h>

// Fixed problem shape (SimpleGNN_35296041238623): N=50000, E=800000, F=64, IN=128
#define NN_MAX 50000
#define NE_MAX 800000
#define ET_MAX (NE_MAX + NN_MAX)

// ---------------- scratch (static device globals; no allocation) -------------
__device__ __align__(16) float    g_xl[NN_MAX * 64];
__device__ __align__(16) float    g_xr[NN_MAX * 64];
__device__ __align__(16) float    g_h [NN_MAX * 64];
__device__ float    g_ex[ET_MAX];        // logits, then exp values
__device__ unsigned g_emax[NN_MAX];      // orderable-uint float max
__device__ float    g_denom[NN_MAX];
__device__ int      g_src[ET_MAX];
__device__ int      g_dst[ET_MAX];

// ---------------- helpers ----------------------------------------------------
__device__ __forceinline__ unsigned f2o(float f) {
    unsigned u = __float_as_uint(f);
    return (u & 0x80000000u) ? ~u : (u | 0x80000000u);
}
__device__ __forceinline__ float o2f(unsigned u) {
    return (u & 0x80000000u) ? __uint_as_float(u & 0x7fffffffu)
                             : __uint_as_float(~u);
}

// ---------------- zero init --------------------------------------------------
// accp == nullptr -> zero g_h; else zero accp (d_out)
__global__ void zero_init(float* accp, int n) {
    float* __restrict__ acc = accp ? accp : g_h;
    int i = blockIdx.x * blockDim.x + threadIdx.x;
    if (i < n) {
        g_emax[i] = 0u;      // below f2o of any finite float; self-loop always updates
        g_denom[i] = 0.0f;
    }
    if (i < n * 64) acc[i] = 0.0f;
}

// ---------------- edge prep: int32 edge_index + self loops -------------------
// edge_index is INT32 (JAX default x64-disabled downcasts jnp.int64 -> int32).
// Clamp defensively: a bad index becomes wrong-but-finite, never a wild load.
__global__ void prep_edges(const int* __restrict__ ei, int E, int n) {
    int i = blockIdx.x * blockDim.x + threadIdx.x;
    if (i < E) {
        int s = ei[i];
        int d = ei[E + i];
        s = (s < 0) ? 0 : ((s >= n) ? n - 1 : s);
        d = (d < 0) ? 0 : ((d >= n) ? n - 1 : d);
        g_src[i] = s;
        g_dst[i] = d;
    }
    if (i < n) {
        g_src[E + i] = i;
        g_dst[E + i] = i;
    }
}

// ---------------- dual GEMM: XL = X@Wl, XR = X@Wr  (Wl,Wr: [K,64]) -----------
// Xin == nullptr -> read from g_h. Block: 256 threads, 32 rows. 2 rows x 8 cols/thread.
template <int K>
__global__ void gemm_dual(const float* Xin,
                          const float* __restrict__ Wl,
                          const float* __restrict__ Wr,
                          int n) {
    const float* __restrict__ X = Xin ? Xin : g_h;
    __shared__ float xs[32][K + 4];
    const int row0 = blockIdx.x * 32;
    const int t = threadIdx.x;

    for (int i = t; i < 32 * K; i += 256) {
        int r = i / K, k = i - r * K;
        int gr = row0 + r;
        xs[r][k] = (gr < n) ? X[gr * K + k] : 0.0f;
    }
    __syncthreads();

    const int rs = t >> 4;          // 0..15 -> rows 2*rs, 2*rs+1
    const int cg = t & 15;          // 0..15 -> col group
    const float* __restrict__ W = (cg < 8) ? Wl : Wr;
    const int c0 = (cg & 7) * 8;

    float acc[2][8];
#pragma unroll
    for (int r = 0; r < 2; r++)
#pragma unroll
        for (int j = 0; j < 8; j++) acc[r][j] = 0.0f;

#pragma unroll 8
    for (int k = 0; k < K; k++) {
        float4 w0 = __ldg((const float4*)&W[k * 64 + c0]);
        float4 w1 = __ldg((const float4*)&W[k * 64 + c0 + 4]);
        float x0 = xs[2 * rs][k];
        float x1 = xs[2 * rs + 1][k];
        acc[0][0] = fmaf(x0, w0.x, acc[0][0]);
        acc[0][1] = fmaf(x0, w0.y, acc[0][1]);
        acc[0][2] = fmaf(x0, w0.z, acc[0][2]);
        acc[0][3] = fmaf(x0, w0.w, acc[0][3]);
        acc[0][4] = fmaf(x0, w1.x, acc[0][4]);
        acc[0][5] = fmaf(x0, w1.y, acc[0][5]);
        acc[0][6] = fmaf(x0, w1.z, acc[0][6]);
        acc[0][7] = fmaf(x0, w1.w, acc[0][7]);
        acc[1][0] = fmaf(x1, w0.x, acc[1][0]);
        acc[1][1] = fmaf(x1, w0.y, acc[1][1]);
        acc[1][2] = fmaf(x1, w0.z, acc[1][2]);
        acc[1][3] = fmaf(x1, w0.w, acc[1][3]);
        acc[1][4] = fmaf(x1, w1.x, acc[1][4]);
        acc[1][5] = fmaf(x1, w1.y, acc[1][5]);
        acc[1][6] = fmaf(x1, w1.z, acc[1][6]);
        acc[1][7] = fmaf(x1, w1.w, acc[1][7]);
    }

    float* __restrict__ O = (cg < 8) ? g_xl : g_xr;
#pragma unroll
    for (int r = 0; r < 2; r++) {
        int gr = row0 + 2 * rs + r;
        if (gr < n) {
            float4 v0 = make_float4(acc[r][0], acc[r][1], acc[r][2], acc[r][3]);
            float4 v1 = make_float4(acc[r][4], acc[r][5], acc[r][6], acc[r][7]);
            *(float4*)&O[gr * 64 + c0]     = v0;
            *(float4*)&O[gr * 64 + c0 + 4] = v1;
        }
    }
}

// ---------------- pass A: per-edge logit + segment max -----------------------
// one warp per edge; lane handles 2 feature columns
__global__ void edge_logits(const float* __restrict__ att, int etot) {
    int gw = (blockIdx.x * blockDim.x + threadIdx.x) >> 5;
    int lane = threadIdx.x & 31;
    if (gw >= etot) return;
    int s = g_src[gw], d = g_dst[gw];
    float2 a = *(const float2*)&g_xl[s * 64 + lane * 2];
    float2 b = *(const float2*)&g_xr[d * 64 + lane * 2];
    float ux = a.x + b.x, uy = a.y + b.y;
    ux = (ux > 0.0f) ? ux : 0.2f * ux;
    uy = (uy > 0.0f) ? uy : 0.2f * uy;
    float2 av = *(const float2*)&att[lane * 2];
    float p = ux * av.x + uy * av.y;
#pragma unroll
    for (int o = 16; o > 0; o >>= 1) p += __shfl_xor_sync(0xffffffffu, p, o);
    if (lane == 0) {
        g_ex[gw] = p;
        atomicMax(&g_emax[d], f2o(p));
    }
}

// ---------------- pass B: exp + segment sum ----------------------------------
__global__ void edge_softmax(int etot) {
    int i = blockIdx.x * blockDim.x + threadIdx.x;
    if (i >= etot) return;
    int d = g_dst[i];
    float m = o2f(g_emax[d]);
    float ex = __expf(g_ex[i] - m);
    g_ex[i] = ex;
    atomicAdd(&g_denom[d], ex);
}

// ---------------- pass C: weighted scatter-add -------------------------------
// 16 threads per edge, 4 columns each, scalar atomics.
// outp == nullptr -> accumulate into g_h.
__global__ void edge_aggregate(float* outp, int etot) {
    float* __restrict__ out = outp ? outp : g_h;
    int t = blockIdx.x * blockDim.x + threadIdx.x;
    int e = t >> 4;
    if (e >= etot) return;
    int c = (t & 15) << 2;
    int s = g_src[e], d = g_dst[e];
    float alpha = g_ex[e] / (g_denom[d] + 1e-16f);
    float4 v = *(const float4*)&g_xl[s * 64 + c];
    float* o = &out[d * 64 + c];
    atomicAdd(o + 0, alpha * v.x);
    atomicAdd(o + 1, alpha * v.y);
    atomicAdd(o + 2, alpha * v.z);
    atomicAdd(o + 3, alpha * v.w);
}

// ---------------- finalize ----------------------------------------------------
__global__ void finalize_relu_bias(const float* __restrict__ bias, int n) {
    int i = blockIdx.x * blockDim.x + threadIdx.x;
    if (i >= n * 64) return;
    float v = g_h[i] + bias[i & 63];
    g_h[i] = (v > 0.0f) ? v : 0.0f;
}
__global__ void finalize_bias(float* __restrict__ out,
                              const float* __restrict__ bias, int n) {
    int i = blockIdx.x * blockDim.x + threadIdx.x;
    if (i >= n * 64) return;
    out[i] += bias[i & 63];
}

// ---------------- launch ------------------------------------------------------
// ONLY kernel launches here — no other CUDA API calls of any kind.
extern "C" void kernel_launch(void* const* d_in, const int* in_sizes, int n_in,
                              void* d_out, int out_size) {
    const float* x    = (const float*)d_in[0];
    const int*   ei   = (const int*)d_in[1];    // int32! (JAX x64 disabled)
    const float* W1l  = (const float*)d_in[2];
    const float* W1r  = (const float*)d_in[3];
    const float* att1 = (const float*)d_in[4];
    const float* b1   = (const float*)d_in[5];
    const float* W2l  = (const float*)d_in[6];
    const float* W2r  = (const float*)d_in[7];
    const float* att2 = (const float*)d_in[8];
    const float* b2   = (const float*)d_in[9];

    const int n    = in_sizes[0] / 128;   // 50000
    const int E    = in_sizes[1] / 2;     // 800000
    const int etot = E + n;

    float* out = (float*)d_out;

    const int B = 256;
    const int gridNF = (n * 64 + B - 1) / B;

    // edge conversion + self loops
    prep_edges<<<(E + B - 1) / B, B>>>(ei, E, n);

    // ---------------- layer 1 (accumulator: g_h via nullptr) ----------------
    zero_init<<<gridNF, B>>>(nullptr, n);
    gemm_dual<128><<<(n + 31) / 32, 256>>>(x, W1l, W1r, n);
    edge_logits<<<((etot * 32) + B - 1) / B, B>>>(att1, etot);
    edge_softmax<<<(etot + B - 1) / B, B>>>(etot);
    edge_aggregate<<<((etot * 16) + B - 1) / B, B>>>(nullptr, etot);
    finalize_relu_bias<<<gridNF, B>>>(b1, n);

    // ---------------- layer 2 (accumulator: d_out) ----------------
    zero_init<<<gridNF, B>>>(out, n);
    gemm_dual<64><<<(n + 31) / 32, 256>>>(nullptr, W2l, W2r, n);
    edge_logits<<<((etot * 32) + B - 1) / B, B>>>(att2, etot);
    edge_softmax<<<(etot + B - 1) / B, B>>>(etot);
    edge_aggregate<<<((etot * 16) + B - 1) / B, B>>>(out, etot);
    finalize_bias<<<gridNF, B>>>(out, b2, n);
}

// round 7
// speedup vs baseline: 1.2105x; 1.2105x over previous
#include <cuda_runtime.h>

// Fixed problem shape: N=50000, E=800000, F=64, IN=128
#define NN_MAX 50000
#define NE_MAX 800000
#define ET_MAX (NE_MAX + NN_MAX)
#define SCAN_B 1024
#define NBLK ((NN_MAX + SCAN_B - 1) / SCAN_B)   // 49

// ---------------- scratch (static device globals; no allocation) -------------
__device__ __align__(16) float g_xl[NN_MAX * 64];
__device__ __align__(16) float g_xr[NN_MAX * 64];
__device__ __align__(16) float g_h [NN_MAX * 64];
__device__ float g_ex[ET_MAX];     // per-edge logits (CSR order)
__device__ int   g_srcs[ET_MAX];   // src ids sorted by dst (CSR adjacency)
__device__ int   g_es[ET_MAX];     // raw src
__device__ int   g_ed[ET_MAX];     // raw dst
__device__ int   g_cnt[NN_MAX];    // in-degree (incl self loop)
__device__ int   g_row[NN_MAX];    // CSR row offsets (exclusive scan of cnt)
__device__ int   g_cur[NN_MAX];    // scatter cursors
__device__ int   g_bsum[NBLK];

// ---------------- CSR build --------------------------------------------------
__global__ void zero_cnt(int n) {
    int i = blockIdx.x * blockDim.x + threadIdx.x;
    if (i < n) { g_cnt[i] = 0; g_cur[i] = 0; }
}

// int32 edge_index (JAX x64 disabled). Clamp defensively; add self loops.
__global__ void prep_hist(const int* __restrict__ ei, int E, int n) {
    int i = blockIdx.x * blockDim.x + threadIdx.x;
    if (i < E) {
        int s = ei[i], d = ei[E + i];
        s = min(max(s, 0), n - 1);
        d = min(max(d, 0), n - 1);
        g_es[i] = s; g_ed[i] = d;
        atomicAdd(&g_cnt[d], 1);
    }
    if (i < n) {
        g_es[E + i] = i; g_ed[E + i] = i;
        atomicAdd(&g_cnt[i], 1);
    }
}

__global__ void scan1(int n) {
    __shared__ int sm[SCAN_B];
    int tid = threadIdx.x, i = blockIdx.x * SCAN_B + tid;
    int v = (i < n) ? g_cnt[i] : 0;
    sm[tid] = v; __syncthreads();
    for (int off = 1; off < SCAN_B; off <<= 1) {
        int t = (tid >= off) ? sm[tid - off] : 0;
        __syncthreads();
        sm[tid] += t; __syncthreads();
    }
    if (i < n) g_row[i] = sm[tid] - v;          // exclusive
    if (tid == SCAN_B - 1) g_bsum[blockIdx.x] = sm[tid];
}
__global__ void scan2() {
    if (threadIdx.x == 0) {
        int acc = 0;
        for (int b = 0; b < NBLK; b++) { int t = g_bsum[b]; g_bsum[b] = acc; acc += t; }
    }
}
__global__ void scan3(int n) {
    int i = blockIdx.x * blockDim.x + threadIdx.x;
    if (i < n) g_row[i] += g_bsum[i >> 10];
}

__global__ void scatter(int etot) {
    int i = blockIdx.x * blockDim.x + threadIdx.x;
    if (i < etot) {
        int d = g_ed[i];
        int pos = g_row[d] + atomicAdd(&g_cur[d], 1);
        g_srcs[pos] = g_es[i];
    }
}

// ---------------- dual GEMM: XL = X@Wl, XR = X@Wr  (Wl,Wr: [K,64]) -----------
// Xin == nullptr -> read from g_h. 256 thr, 32 rows/block, 2 rows x 8 cols/thread.
template <int K>
__global__ void gemm_dual(const float* Xin,
                          const float* __restrict__ Wl,
                          const float* __restrict__ Wr,
                          int n) {
    const float* __restrict__ X = Xin ? Xin : g_h;
    __shared__ float xs[32][K + 4];
    const int row0 = blockIdx.x * 32;
    const int t = threadIdx.x;

    for (int i = t; i < 32 * K; i += 256) {
        int r = i / K, k = i - r * K;
        int gr = row0 + r;
        xs[r][k] = (gr < n) ? X[gr * K + k] : 0.0f;
    }
    __syncthreads();

    const int rs = t >> 4;
    const int cg = t & 15;
    const float* __restrict__ W = (cg < 8) ? Wl : Wr;
    const int c0 = (cg & 7) * 8;

    float acc[2][8];
#pragma unroll
    for (int r = 0; r < 2; r++)
#pragma unroll
        for (int j = 0; j < 8; j++) acc[r][j] = 0.0f;

#pragma unroll 8
    for (int k = 0; k < K; k++) {
        float4 w0 = __ldg((const float4*)&W[k * 64 + c0]);
        float4 w1 = __ldg((const float4*)&W[k * 64 + c0 + 4]);
        float x0 = xs[2 * rs][k];
        float x1 = xs[2 * rs + 1][k];
        acc[0][0] = fmaf(x0, w0.x, acc[0][0]);
        acc[0][1] = fmaf(x0, w0.y, acc[0][1]);
        acc[0][2] = fmaf(x0, w0.z, acc[0][2]);
        acc[0][3] = fmaf(x0, w0.w, acc[0][3]);
        acc[0][4] = fmaf(x0, w1.x, acc[0][4]);
        acc[0][5] = fmaf(x0, w1.y, acc[0][5]);
        acc[0][6] = fmaf(x0, w1.z, acc[0][6]);
        acc[0][7] = fmaf(x0, w1.w, acc[0][7]);
        acc[1][0] = fmaf(x1, w0.x, acc[1][0]);
        acc[1][1] = fmaf(x1, w0.y, acc[1][1]);
        acc[1][2] = fmaf(x1, w0.z, acc[1][2]);
        acc[1][3] = fmaf(x1, w0.w, acc[1][3]);
        acc[1][4] = fmaf(x1, w1.x, acc[1][4]);
        acc[1][5] = fmaf(x1, w1.y, acc[1][5]);
        acc[1][6] = fmaf(x1, w1.z, acc[1][6]);
        acc[1][7] = fmaf(x1, w1.w, acc[1][7]);
    }

    float* __restrict__ O = (cg < 8) ? g_xl : g_xr;
#pragma unroll
    for (int r = 0; r < 2; r++) {
        int gr = row0 + 2 * rs + r;
        if (gr < n) {
            *(float4*)&O[gr * 64 + c0]     = make_float4(acc[r][0], acc[r][1], acc[r][2], acc[r][3]);
            *(float4*)&O[gr * 64 + c0 + 4] = make_float4(acc[r][4], acc[r][5], acc[r][6], acc[r][7]);
        }
    }
}

// ---------------- fused per-node GATv2 pass ----------------------------------
// One warp per node. Pass 1: logits + online softmax stats. Pass 2: weighted
// aggregation. No atomics; accumulator lives in registers.
__global__ void node_fused(const float* __restrict__ att,
                           const float* __restrict__ bias,
                           float* outp, int do_relu, int n) {
    float* __restrict__ out = outp ? outp : g_h;
    int node = (blockIdx.x * blockDim.x + threadIdx.x) >> 5;
    int lane = threadIdx.x & 31;
    if (node >= n) return;

    const int beg = g_row[node];
    const int end = beg + g_cnt[node];

    float2 xr = *(const float2*)&g_xr[node * 64 + lane * 2];
    float2 av = *(const float2*)&att[lane * 2];

    // ---- pass 1: logits + online max/sum ----
    float m = -3.402823e38f, ssum = 0.0f;
    int k = beg;
    for (; k + 1 < end; k += 2) {
        int s0 = g_srcs[k], s1 = g_srcs[k + 1];
        float2 a0 = *(const float2*)&g_xl[s0 * 64 + lane * 2];
        float2 a1 = *(const float2*)&g_xl[s1 * 64 + lane * 2];
        float u0x = a0.x + xr.x, u0y = a0.y + xr.y;
        float u1x = a1.x + xr.x, u1y = a1.y + xr.y;
        u0x = (u0x > 0.0f) ? u0x : 0.2f * u0x;
        u0y = (u0y > 0.0f) ? u0y : 0.2f * u0y;
        u1x = (u1x > 0.0f) ? u1x : 0.2f * u1x;
        u1y = (u1y > 0.0f) ? u1y : 0.2f * u1y;
        float p0 = u0x * av.x + u0y * av.y;
        float p1 = u1x * av.x + u1y * av.y;
#pragma unroll
        for (int o = 16; o > 0; o >>= 1) {
            p0 += __shfl_xor_sync(0xffffffffu, p0, o);
            p1 += __shfl_xor_sync(0xffffffffu, p1, o);
        }
        if (lane == 0) { g_ex[k] = p0; g_ex[k + 1] = p1; }
        float mn = fmaxf(m, fmaxf(p0, p1));
        ssum = ssum * __expf(m - mn) + __expf(p0 - mn) + __expf(p1 - mn);
        m = mn;
    }
    if (k < end) {
        int s0 = g_srcs[k];
        float2 a0 = *(const float2*)&g_xl[s0 * 64 + lane * 2];
        float ux = a0.x + xr.x, uy = a0.y + xr.y;
        ux = (ux > 0.0f) ? ux : 0.2f * ux;
        uy = (uy > 0.0f) ? uy : 0.2f * uy;
        float p0 = ux * av.x + uy * av.y;
#pragma unroll
        for (int o = 16; o > 0; o >>= 1) p0 += __shfl_xor_sync(0xffffffffu, p0, o);
        if (lane == 0) g_ex[k] = p0;
        float mn = fmaxf(m, p0);
        ssum = ssum * __expf(m - mn) + __expf(p0 - mn);
        m = mn;
    }

    const float inv = 1.0f / (ssum + 1e-16f);

    // ---- pass 2: weighted aggregation ----
    float2 acc = make_float2(0.0f, 0.0f);
    for (k = beg; k + 1 < end; k += 2) {
        float pv0 = 0.0f, pv1 = 0.0f;
        if (lane == 0) { pv0 = g_ex[k]; pv1 = g_ex[k + 1]; }   // own stores: coherent
        pv0 = __shfl_sync(0xffffffffu, pv0, 0);
        pv1 = __shfl_sync(0xffffffffu, pv1, 0);
        float al0 = __expf(pv0 - m) * inv;
        float al1 = __expf(pv1 - m) * inv;
        int s0 = g_srcs[k], s1 = g_srcs[k + 1];
        float2 a0 = *(const float2*)&g_xl[s0 * 64 + lane * 2];
        float2 a1 = *(const float2*)&g_xl[s1 * 64 + lane * 2];
        acc.x = fmaf(al0, a0.x, fmaf(al1, a1.x, acc.x));
        acc.y = fmaf(al0, a0.y, fmaf(al1, a1.y, acc.y));
    }
    if (k < end) {
        float pv0 = 0.0f;
        if (lane == 0) pv0 = g_ex[k];
        pv0 = __shfl_sync(0xffffffffu, pv0, 0);
        float al0 = __expf(pv0 - m) * inv;
        int s0 = g_srcs[k];
        float2 a0 = *(const float2*)&g_xl[s0 * 64 + lane * 2];
        acc.x = fmaf(al0, a0.x, acc.x);
        acc.y = fmaf(al0, a0.y, acc.y);
    }

    float2 bv = *(const float2*)&bias[lane * 2];
    acc.x += bv.x; acc.y += bv.y;
    if (do_relu) { acc.x = fmaxf(acc.x, 0.0f); acc.y = fmaxf(acc.y, 0.0f); }
    *(float2*)&out[node * 64 + lane * 2] = acc;
}

// ---------------- launch ------------------------------------------------------
extern "C" void kernel_launch(void* const* d_in, const int* in_sizes, int n_in,
                              void* d_out, int out_size) {
    const float* x    = (const float*)d_in[0];
    const int*   ei   = (const int*)d_in[1];    // int32 (JAX x64 disabled)
    const float* W1l  = (const float*)d_in[2];
    const float* W1r  = (const float*)d_in[3];
    const float* att1 = (const float*)d_in[4];
    const float* b1   = (const float*)d_in[5];
    const float* W2l  = (const float*)d_in[6];
    const float* W2r  = (const float*)d_in[7];
    const float* att2 = (const float*)d_in[8];
    const float* b2   = (const float*)d_in[9];

    const int n    = in_sizes[0] / 128;   // 50000
    const int E    = in_sizes[1] / 2;     // 800000
    const int etot = E + n;

    float* out = (float*)d_out;
    const int B = 256;

    // ---- CSR build (once; reused by both layers) ----
    zero_cnt<<<(n + B - 1) / B, B>>>(n);
    prep_hist<<<(E + B - 1) / B, B>>>(ei, E, n);
    scan1<<<NBLK, SCAN_B>>>(n);
    scan2<<<1, 32>>>();
    scan3<<<(n + B - 1) / B, B>>>(n);
    scatter<<<(etot + B - 1) / B, B>>>(etot);

    const int gridNode = (n * 32 + B - 1) / B;

    // ---- layer 1 ----
    gemm_dual<128><<<(n + 31) / 32, 256>>>(x, W1l, W1r, n);
    node_fused<<<gridNode, B>>>(att1, b1, nullptr, 1, n);

    // ---- layer 2 ----
    gemm_dual<64><<<(n + 31) / 32, 256>>>(nullptr, W2l, W2r, n);
    node_fused<<<gridNode, B>>>(att2, b2, out, 0, n);
}

// round 8
// speedup vs baseline: 2.2333x; 1.8450x over previous
#include <cuda_runtime.h>

// Fixed problem shape: N=50000, E=800000, F=64, IN=128
#define NN_MAX 50000
#define NE_MAX 800000
#define ET_MAX (NE_MAX + NN_MAX)
#define SCAN_B 1024
#define NBLK ((NN_MAX + SCAN_B - 1) / SCAN_B)   // 49

// ---------------- scratch (static device globals; no allocation) -------------
__device__ __align__(16) float g_xl[NN_MAX * 64];
__device__ __align__(16) float g_xr[NN_MAX * 64];
__device__ __align__(16) float g_h [NN_MAX * 64];
__device__ int   g_srcs[ET_MAX];   // src ids sorted by dst (CSR adjacency)
__device__ int   g_es[ET_MAX];     // raw src
__device__ int   g_ed[ET_MAX];     // raw dst
__device__ int   g_cnt[NN_MAX];    // in-degree (incl self loop)
__device__ int   g_row[NN_MAX];    // CSR row offsets (exclusive scan of cnt)
__device__ int   g_cur[NN_MAX];    // scatter cursors
__device__ int   g_bsum[NBLK];

// ---------------- CSR build --------------------------------------------------
__global__ void zero_cnt(int n) {
    int i = blockIdx.x * blockDim.x + threadIdx.x;
    if (i < n) { g_cnt[i] = 0; g_cur[i] = 0; }
}

// int32 edge_index (JAX x64 disabled). Clamp defensively; add self loops.
__global__ void prep_hist(const int* __restrict__ ei, int E, int n) {
    int i = blockIdx.x * blockDim.x + threadIdx.x;
    if (i < E) {
        int s = ei[i], d = ei[E + i];
        s = min(max(s, 0), n - 1);
        d = min(max(d, 0), n - 1);
        g_es[i] = s; g_ed[i] = d;
        atomicAdd(&g_cnt[d], 1);
    }
    if (i < n) {
        g_es[E + i] = i; g_ed[E + i] = i;
        atomicAdd(&g_cnt[i], 1);
    }
}

__global__ void scan1(int n) {
    __shared__ int sm[SCAN_B];
    int tid = threadIdx.x, i = blockIdx.x * SCAN_B + tid;
    int v = (i < n) ? g_cnt[i] : 0;
    sm[tid] = v; __syncthreads();
    for (int off = 1; off < SCAN_B; off <<= 1) {
        int t = (tid >= off) ? sm[tid - off] : 0;
        __syncthreads();
        sm[tid] += t; __syncthreads();
    }
    if (i < n) g_row[i] = sm[tid] - v;          // exclusive
    if (tid == SCAN_B - 1) g_bsum[blockIdx.x] = sm[tid];
}
__global__ void scan2() {
    if (threadIdx.x == 0) {
        int acc = 0;
        for (int b = 0; b < NBLK; b++) { int t = g_bsum[b]; g_bsum[b] = acc; acc += t; }
    }
}
__global__ void scan3(int n) {
    int i = blockIdx.x * blockDim.x + threadIdx.x;
    if (i < n) g_row[i] += g_bsum[i >> 10];
}

__global__ void scatter(int etot) {
    int i = blockIdx.x * blockDim.x + threadIdx.x;
    if (i < etot) {
        int d = g_ed[i];
        int pos = g_row[d] + atomicAdd(&g_cur[d], 1);
        g_srcs[pos] = g_es[i];
    }
}

// ---------------- dual GEMM: XL = X@Wl, XR = X@Wr  (Wl,Wr: [K,64]) -----------
template <int K>
__global__ __launch_bounds__(256) void gemm_dual(const float* Xin,
                          const float* __restrict__ Wl,
                          const float* __restrict__ Wr,
                          int n) {
    const float* __restrict__ X = Xin ? Xin : g_h;
    __shared__ float xs[32][K + 4];
    const int row0 = blockIdx.x * 32;
    const int t = threadIdx.x;

    for (int i = t; i < 32 * K; i += 256) {
        int r = i / K, k = i - r * K;
        int gr = row0 + r;
        xs[r][k] = (gr < n) ? X[gr * K + k] : 0.0f;
    }
    __syncthreads();

    const int rs = t >> 4;
    const int cg = t & 15;
    const float* __restrict__ W = (cg < 8) ? Wl : Wr;
    const int c0 = (cg & 7) * 8;

    float acc[2][8];
#pragma unroll
    for (int r = 0; r < 2; r++)
#pragma unroll
        for (int j = 0; j < 8; j++) acc[r][j] = 0.0f;

#pragma unroll 8
    for (int k = 0; k < K; k++) {
        float4 w0 = __ldg((const float4*)&W[k * 64 + c0]);
        float4 w1 = __ldg((const float4*)&W[k * 64 + c0 + 4]);
        float x0 = xs[2 * rs][k];
        float x1 = xs[2 * rs + 1][k];
        acc[0][0] = fmaf(x0, w0.x, acc[0][0]);
        acc[0][1] = fmaf(x0, w0.y, acc[0][1]);
        acc[0][2] = fmaf(x0, w0.z, acc[0][2]);
        acc[0][3] = fmaf(x0, w0.w, acc[0][3]);
        acc[0][4] = fmaf(x0, w1.x, acc[0][4]);
        acc[0][5] = fmaf(x0, w1.y, acc[0][5]);
        acc[0][6] = fmaf(x0, w1.z, acc[0][6]);
        acc[0][7] = fmaf(x0, w1.w, acc[0][7]);
        acc[1][0] = fmaf(x1, w0.x, acc[1][0]);
        acc[1][1] = fmaf(x1, w0.y, acc[1][1]);
        acc[1][2] = fmaf(x1, w0.z, acc[1][2]);
        acc[1][3] = fmaf(x1, w0.w, acc[1][3]);
        acc[1][4] = fmaf(x1, w1.x, acc[1][4]);
        acc[1][5] = fmaf(x1, w1.y, acc[1][5]);
        acc[1][6] = fmaf(x1, w1.z, acc[1][6]);
        acc[1][7] = fmaf(x1, w1.w, acc[1][7]);
    }

    float* __restrict__ O = (cg < 8) ? g_xl : g_xr;
#pragma unroll
    for (int r = 0; r < 2; r++) {
        int gr = row0 + 2 * rs + r;
        if (gr < n) {
            *(float4*)&O[gr * 64 + c0]     = make_float4(acc[r][0], acc[r][1], acc[r][2], acc[r][3]);
            *(float4*)&O[gr * 64 + c0 + 4] = make_float4(acc[r][4], acc[r][5], acc[r][6], acc[r][7]);
        }
    }
}

// ---------------- single-pass fused GATv2 node kernel ------------------------
// Warp per node, split in two 16-lane halves; each half handles one edge per
// step (float4/lane = full 256B row). Flash-style online softmax+aggregation:
// ONE sweep over incident edges, no g_ex spill, no atomics.
__device__ __forceinline__ float dot_leaky(float4 a, float4 xr, float4 av) {
    float ux = a.x + xr.x; ux = (ux > 0.0f) ? ux : 0.2f * ux;
    float uy = a.y + xr.y; uy = (uy > 0.0f) ? uy : 0.2f * uy;
    float uz = a.z + xr.z; uz = (uz > 0.0f) ? uz : 0.2f * uz;
    float uw = a.w + xr.w; uw = (uw > 0.0f) ? uw : 0.2f * uw;
    return fmaf(ux, av.x, fmaf(uy, av.y, fmaf(uz, av.z, uw * av.w)));
}

__global__ __launch_bounds__(256) void node_fused(const float* __restrict__ att,
                           const float* __restrict__ bias,
                           float* outp, int do_relu, int n) {
    float* __restrict__ out = outp ? outp : g_h;
    int node = (blockIdx.x * blockDim.x + threadIdx.x) >> 5;
    if (node >= n) return;
    const int lane = threadIdx.x & 31;
    const int half = lane >> 4;          // which edge of the pair
    const int hl   = lane & 15;          // feature group: 4 floats

    const int beg = g_row[node];
    const int deg = g_cnt[node];
    const int end = beg + deg;

    const float4 xr4 = *(const float4*)&g_xr[node * 64 + hl * 4];
    const float4 av4 = *(const float4*)&att[hl * 4];

    float m = -1e30f, ssum = 0.0f;       // finite init: no inf-inf NaN on empty half
    float4 acc = make_float4(0.0f, 0.0f, 0.0f, 0.0f);

    for (int kk = 0; kk < deg; kk += 4) {
        int i0 = beg + kk + half;
        int i1 = beg + kk + 2 + half;
        bool v0 = i0 < end, v1 = i1 < end;
        int s0 = g_srcs[v0 ? i0 : beg];
        int s1 = g_srcs[v1 ? i1 : beg];
        float4 a0 = *(const float4*)&g_xl[s0 * 64 + hl * 4];
        float4 a1 = *(const float4*)&g_xl[s1 * 64 + hl * 4];

        float p0 = dot_leaky(a0, xr4, av4);
        float p1 = dot_leaky(a1, xr4, av4);
#pragma unroll
        for (int o = 1; o < 16; o <<= 1) {
            p0 += __shfl_xor_sync(0xffffffffu, p0, o);
            p1 += __shfl_xor_sync(0xffffffffu, p1, o);
        }
        float q0 = v0 ? p0 : -3.402823e38f;
        float q1 = v1 ? p1 : -3.402823e38f;
        float mn = fmaxf(m, fmaxf(q0, q1));
        float sc = __expf(m - mn);
        float e0 = v0 ? __expf(p0 - mn) : 0.0f;
        float e1 = v1 ? __expf(p1 - mn) : 0.0f;
        ssum = fmaf(ssum, sc, e0 + e1);
        acc.x = fmaf(acc.x, sc, fmaf(e0, a0.x, e1 * a1.x));
        acc.y = fmaf(acc.y, sc, fmaf(e0, a0.y, e1 * a1.y));
        acc.z = fmaf(acc.z, sc, fmaf(e0, a0.z, e1 * a1.z));
        acc.w = fmaf(acc.w, sc, fmaf(e0, a0.w, e1 * a1.w));
        m = mn;
    }

    // combine the two halves (shfl_xor 16 is symmetric: both get same result)
    float m2 = __shfl_xor_sync(0xffffffffu, m, 16);
    float s2 = __shfl_xor_sync(0xffffffffu, ssum, 16);
    float4 ac2;
    ac2.x = __shfl_xor_sync(0xffffffffu, acc.x, 16);
    ac2.y = __shfl_xor_sync(0xffffffffu, acc.y, 16);
    ac2.z = __shfl_xor_sync(0xffffffffu, acc.z, 16);
    ac2.w = __shfl_xor_sync(0xffffffffu, acc.w, 16);
    float mn = fmaxf(m, m2);
    float c1 = __expf(m - mn), c2 = __expf(m2 - mn);
    ssum = ssum * c1 + s2 * c2;
    acc.x = acc.x * c1 + ac2.x * c2;
    acc.y = acc.y * c1 + ac2.y * c2;
    acc.z = acc.z * c1 + ac2.z * c2;
    acc.w = acc.w * c1 + ac2.w * c2;

    const float inv = 1.0f / (ssum + 1e-16f);
    float4 b4 = *(const float4*)&bias[hl * 4];
    float4 r;
    r.x = fmaf(acc.x, inv, b4.x);
    r.y = fmaf(acc.y, inv, b4.y);
    r.z = fmaf(acc.z, inv, b4.z);
    r.w = fmaf(acc.w, inv, b4.w);
    if (do_relu) {
        r.x = fmaxf(r.x, 0.0f); r.y = fmaxf(r.y, 0.0f);
        r.z = fmaxf(r.z, 0.0f); r.w = fmaxf(r.w, 0.0f);
    }
    if (half == 0) *(float4*)&out[node * 64 + hl * 4] = r;
}

// ---------------- launch ------------------------------------------------------
extern "C" void kernel_launch(void* const* d_in, const int* in_sizes, int n_in,
                              void* d_out, int out_size) {
    const float* x    = (const float*)d_in[0];
    const int*   ei   = (const int*)d_in[1];    // int32 (JAX x64 disabled)
    const float* W1l  = (const float*)d_in[2];
    const float* W1r  = (const float*)d_in[3];
    const float* att1 = (const float*)d_in[4];
    const float* b1   = (const float*)d_in[5];
    const float* W2l  = (const float*)d_in[6];
    const float* W2r  = (const float*)d_in[7];
    const float* att2 = (const float*)d_in[8];
    const float* b2   = (const float*)d_in[9];

    const int n    = in_sizes[0] / 128;   // 50000
    const int E    = in_sizes[1] / 2;     // 800000
    const int etot = E + n;

    float* out = (float*)d_out;
    const int B = 256;

    // ---- CSR build (once; reused by both layers) ----
    zero_cnt<<<(n + B - 1) / B, B>>>(n);
    prep_hist<<<(E + B - 1) / B, B>>>(ei, E, n);
    scan1<<<NBLK, SCAN_B>>>(n);
    scan2<<<1, 32>>>();
    scan3<<<(n + B - 1) / B, B>>>(n);
    scatter<<<(etot + B - 1) / B, B>>>(etot);

    const int gridNode = (n * 32 + B - 1) / B;

    // ---- layer 1 ----
    gemm_dual<128><<<(n + 31) / 32, 256>>>(x, W1l, W1r, n);
    node_fused<<<gridNode, B>>>(att1, b1, nullptr, 1, n);

    // ---- layer 2 ----
    gemm_dual<64><<<(n + 31) / 32, 256>>>(nullptr, W2l, W2r, n);
    node_fused<<<gridNode, B>>>(att2, b2, out, 0, n);
}